// round 12
// baseline (speedup 1.0000x reference)
#include <cuda_runtime.h>

#define NN 50000
#define EE 500000
#define SD 128
#define HID 64
#define DEPTH 4
#define CUTF 5.0f
#define PI_F 3.14159265358979f

#define TE 64
#define NT_E ((EE + TE - 1) / TE)
#define TN 64
#define NT_N ((NN + TN - 1) / TN)
#define PERMB ((EE + 255) / 256)

// ---------------- device scratch ----------------
__device__ float g_sbuf[NN * SD];
__device__ float g_vbuf[NN * 9];
__device__ float g_hagg[NN * HID];
__device__ float g_vagg[NN * 9];
__device__ float g_Pa[NN * HID];
__device__ float g_Pb[NN * HID];
__device__ float g_icnt[NN];
__device__ float g_cntC[NN];
__device__ int   g_cnti[NN];      // zero at load; restored by k_permproj each run
__device__ int   g_cur[NN];
__device__ int   g_dstS[EE];
__device__ int   g_srcS[EE];
__device__ float g_Cs[EE];
__device__ float g_dsrt[EE];
__device__ float g_rs[EE * 3];
__device__ float g_Wc[DEPTH * 64 * 64];
__device__ float g_bc[DEPTH * 64];

__device__ __forceinline__ float silu_f(float x) {
    return x / (1.0f + __expf(-x));
}

__device__ __forceinline__ void ffma2(unsigned long long& acc,
                                      unsigned long long a, unsigned long long b) {
    asm("fma.rn.f32x2 %0, %1, %2, %0;" : "+l"(acc) : "l"(a), "l"(b));
}
__device__ __forceinline__ unsigned long long packlo(float x) {
    return (unsigned long long)__float_as_uint(x);
}
__device__ __forceinline__ float f2x_sum(unsigned long long a) {
    float lo = __int_as_float((unsigned)(a & 0xffffffffull));
    float hi = __int_as_float((unsigned)(a >> 32));
    return lo + hi;
}

// ---------------- launch 1: init (copy + zero + degree count) ----------------
__global__ void k_init(const float* __restrict__ s, const float* __restrict__ v,
                       const int* __restrict__ ei) {
    int i = blockIdx.x * blockDim.x + threadIdx.x;
    int stride = gridDim.x * blockDim.x;
    for (int j = i; j < NN * SD; j += stride) g_sbuf[j] = s[j];
    for (int j = i; j < NN * 9; j += stride) { g_vbuf[j] = v[j]; g_vagg[j] = 0.0f; }
    for (int j = i; j < NN * HID; j += stride) g_hagg[j] = 0.0f;
    for (int j = i; j < NN; j += stride) g_cntC[j] = 0.0f;
    for (int j = i; j < EE; j += stride) atomicAdd(&g_cnti[ei[j]], 1);
}

// ---------------- launch 2: scan ----------------
__global__ void k_scan() {
    __shared__ int sh[1024];
    __shared__ int carry;
    int tid = threadIdx.x;
    if (tid == 0) carry = 0;
    __syncthreads();
    for (int base = 0; base < NN; base += 1024) {
        int i = base + tid;
        int x = (i < NN) ? g_cnti[i] : 0;
        sh[tid] = x;
        __syncthreads();
        for (int off = 1; off < 1024; off <<= 1) {
            int t = (tid >= off) ? sh[tid - off] : 0;
            __syncthreads();
            sh[tid] += t;
            __syncthreads();
        }
        if (i < NN) {
            g_cur[i] = carry + sh[tid] - x;
            g_icnt[i] = 1.0f / fmaxf((float)x, 1.0f);
        }
        __syncthreads();
        if (tid == 1023) carry += sh[1023];
        __syncthreads();
    }
}

// ---------------- proj body ----------------
#define P_W 0
#define P_X (P_W + 128 * 132)
#define P_TOT (P_X + 64 * 132)

__device__ void proj_body(float* sm, const float* __restrict__ W1, int tileIdx) {
    float* Ws = sm + P_W;
    float* Xt = sm + P_X;
    const int tid = threadIdx.x;
    for (int i = tid; i < 128 * 128; i += 256) {
        int k = i >> 7, o = i & 127;
        float w = (o < 64) ? W1[k * 64 + o] : W1[(128 + k) * 64 + (o - 64)];
        Ws[o * 132 + k] = w;
    }
    const int wid = tid >> 5, lane = tid & 31;
    const int base = tileIdx * TN;
    const int nNd = min(TN, NN - base);
    for (int ii = wid; ii < TN; ii += 8) {
        const int n = base + ii;
        const bool valid = (ii < nNd);
        const float4* sp = (const float4*)&g_sbuf[(valid ? n : 0) * SD];
        float4 x = sp[lane];
        if (!valid) x = make_float4(0.f, 0.f, 0.f, 0.f);
        *(float4*)(Xt + ii * 132 + lane * 4) = x;
    }
    __syncthreads();

    const int oc = tid & 31;
    const int eg = tid >> 5;
    unsigned long long acc[8][4];
    #pragma unroll
    for (int i = 0; i < 8; i++)
        #pragma unroll
        for (int j = 0; j < 4; j++) acc[i][j] = 0ull;

    #pragma unroll 2
    for (int k = 0; k < 128; k += 4) {
        ulonglong2 w[4];
        #pragma unroll
        for (int j = 0; j < 4; j++)
            w[j] = *(const ulonglong2*)(Ws + (oc + 32 * j) * 132 + k);
        #pragma unroll
        for (int i = 0; i < 8; i++) {
            ulonglong2 x = *(const ulonglong2*)(Xt + (eg * 8 + i) * 132 + k);
            #pragma unroll
            for (int j = 0; j < 4; j++) {
                ffma2(acc[i][j], x.x, w[j].x);
                ffma2(acc[i][j], x.y, w[j].y);
            }
        }
    }
    #pragma unroll
    for (int i = 0; i < 8; i++) {
        const int n = base + eg * 8 + i;
        if (eg * 8 + i < nNd) {
            #pragma unroll
            for (int j = 0; j < 4; j++) {
                const int o = oc + 32 * j;
                float val = f2x_sum(acc[i][j]);
                if (o < 64) g_Pa[n * HID + o] = val;
                else        g_Pb[n * HID + (o - 64)] = val;
            }
        }
    }
}

// ---------------- launch 3: perm + layer-0 proj + cnti restore ----------------
__global__ void __launch_bounds__(256, 2) k_permproj(
    const int* __restrict__ ei, const float* __restrict__ d,
    const float* __restrict__ r, const float* __restrict__ W1)
{
    extern __shared__ float sm[];
    if (blockIdx.x < NT_N) {
        proj_body(sm, W1, blockIdx.x);
    } else {
        int e = (blockIdx.x - NT_N) * 256 + threadIdx.x;
        if (e < EE) {
            int dst = ei[e];
            int pos = atomicAdd(&g_cur[dst], 1);
            g_dstS[pos] = dst;
            g_srcS[pos] = ei[EE + e];
            float dd = d[e];
            g_dsrt[pos] = dd;
            float c = (dd < CUTF) ? 0.5f * (cosf(PI_F * dd / CUTF) + 1.0f) : 0.0f;
            g_Cs[pos] = c;
            atomicAdd(&g_cntC[dst], c);
            g_rs[pos * 3 + 0] = r[e * 3 + 0];
            g_rs[pos * 3 + 1] = r[e * 3 + 1];
            g_rs[pos * 3 + 2] = r[e * 3 + 2];
        }
        if (e < NN) g_cnti[e] = 0;   // restore for next graph replay
    }
}

__global__ void __launch_bounds__(256, 2) k_proj(const float* __restrict__ W1) {
    extern __shared__ float sm[];
    proj_body(sm, W1, blockIdx.x);
}

// Wc[l] = W3s[l] @ Wn1b[l] ; bc[l] = b3s[l] @ Wn1b[l]
__global__ void k_wc(const float* __restrict__ W3, const float* __restrict__ b3,
                     const float* __restrict__ Wn1) {
    const int l = blockIdx.x;
    const float* w3 = W3 + l * 64 * 134;
    const float* wn1b = Wn1 + l * 256 * 64 + 128 * 64;
    const float* b3l = b3 + l * 134;
    const int tid = threadIdx.x;
    const int o = tid & 63;
    for (int h = tid >> 6; h < 64; h += 4) {
        float acc = 0.0f;
        for (int m = 0; m < 128; m++)
            acc += w3[h * 134 + m] * wn1b[m * 64 + o];
        g_Wc[l * 4096 + h * 64 + o] = acc;
    }
    if (tid < 64) {
        float acc = 0.0f;
        for (int m = 0; m < 128; m++) acc += b3l[m] * wn1b[m * 64 + tid];
        g_bc[l * 64 + tid] = acc;
    }
}

__global__ void k_out(float* __restrict__ out) {
    int i = blockIdx.x * blockDim.x + threadIdx.x;
    int stride = gridDim.x * blockDim.x;
    for (int j = i; j < NN * SD; j += stride) out[j] = g_sbuf[j];
    for (int j = i; j < NN * 9; j += stride) out[NN * SD + j] = g_vbuf[j];
}

// ---------------- edge kernel (unchanged from R10 winner) ----------------
#define E_W2T 0
#define E_W3G (E_W2T + 4352)
#define E_B1  (E_W3G + 416)
#define E_B2  (E_B1 + 64)
#define E_B3G (E_B2 + 64)
#define E_W1D (E_B3G + 16)
#define E_H1  (E_W1D + 64)
#define E_H2  (E_H1 + 4352)
#define E_CS  (E_H2 + 4352)
#define E_DS  (E_CS + 64)
#define E_SS  (E_DS + 64)
#define E_PBN (E_SS + 64)
#define E_TOT (E_PBN + 4096)            // 17968 floats = 71872 B

__device__ __forceinline__ void prefetch_pb(float* PbN, int ntile, int tid) {
    if (ntile < NT_E) {
        const int base2 = ntile * TE;
        const int e = tid >> 2;
        const int epos = min(base2 + e, EE - 1);
        const int se = g_srcS[epos];
        const int f0 = (tid & 3) * 16;
        const float* gp = &g_Pb[se * HID + f0];
        unsigned saddr = (unsigned)__cvta_generic_to_shared(PbN + e * 64 + f0);
        #pragma unroll
        for (int c = 0; c < 4; c++)
            asm volatile("cp.async.cg.shared.global [%0], [%1], 16;"
                         :: "r"(saddr + c * 16), "l"(gp + c * 4) : "memory");
    }
    asm volatile("cp.async.commit_group;" ::: "memory");
}

__global__ void __launch_bounds__(256, 3) k_edge(
    const float* __restrict__ W1, const float* __restrict__ b1,
    const float* __restrict__ W2, const float* __restrict__ b2,
    const float* __restrict__ W3, const float* __restrict__ b3)
{
    extern __shared__ float sm[];
    float* W2t = sm + E_W2T;
    float* W3g = sm + E_W3G;
    float* b1s = sm + E_B1;
    float* b2s = sm + E_B2;
    float* b3g = sm + E_B3G;
    float* w1d = sm + E_W1D;
    float* H1e = sm + E_H1;
    float* H2e = sm + E_H2;
    float* CS  = sm + E_CS;
    int*   dstSh = (int*)(sm + E_DS);
    int*   srcSh = (int*)(sm + E_SS);
    float* PbN = sm + E_PBN;

    const int tid = threadIdx.x;

    for (int i = tid; i < 64 * 64; i += 256) {
        int k = i >> 6, o = i & 63;
        W2t[o * 68 + k] = W2[k * 64 + o];
    }
    for (int i = tid; i < 6 * 64; i += 256) {
        int o = i % 6, k = i / 6;
        W3g[o * 68 + k] = W3[k * 134 + 128 + o];
    }
    if (tid < 64) {
        b1s[tid] = b1[tid];
        b2s[tid] = b2[tid];
        w1d[tid] = W1[256 * 64 + tid];
    }
    if (tid < 6) b3g[tid] = b3[128 + tid];

    const int wid = tid >> 5, lane = tid & 31;

    prefetch_pb(PbN, blockIdx.x, tid);

    for (int tile = blockIdx.x; tile < NT_E; tile += gridDim.x) {
        const int base = tile * TE;
        const int nE = min(TE, EE - base);

        asm volatile("cp.async.wait_group 0;" ::: "memory");
        __syncthreads();

        // ---- P1: gather + silu -> H1e [e][k] ----
        #pragma unroll 2
        for (int i = 0; i < 8; i++) {
            const int ee = wid * 8 + i;
            const int epos = base + ee;
            const bool valid = (ee < nE);
            int dst = 0, src = 0;
            float dd = 0.0f;
            if (valid) { dst = g_dstS[epos]; src = g_srcS[epos]; dd = g_dsrt[epos]; }
            const float2 a = ((const float2*)&g_Pa[dst * HID])[lane];
            const float2 b = ((const float2*)(PbN + ee * 64))[lane];
            const int k0 = lane * 2;
            float h0 = a.x + b.x + dd * w1d[k0] + b1s[k0];
            float h1 = a.y + b.y + dd * w1d[k0 + 1] + b1s[k0 + 1];
            float2 hv;
            hv.x = valid ? silu_f(h0) : 0.0f;
            hv.y = valid ? silu_f(h1) : 0.0f;
            *(float2*)(H1e + ee * 68 + k0) = hv;
            if (lane == 0) {
                CS[ee] = valid ? g_Cs[epos] : 0.0f;
                dstSh[ee] = dst; srcSh[ee] = src;
            }
        }
        __syncthreads();

        prefetch_pb(PbN, tile + gridDim.x, tid);

        // ---- P2: GEMM2 -> H2e ----
        {
            const int oc = tid & 15;
            const int eg = tid >> 4;
            unsigned long long acc[4][4];
            #pragma unroll
            for (int i = 0; i < 4; i++)
                #pragma unroll
                for (int j = 0; j < 4; j++) acc[i][j] = packlo(b2s[oc + 16 * j]);
            #pragma unroll 4
            for (int k = 0; k < 64; k += 4) {
                ulonglong2 w[4];
                #pragma unroll
                for (int j = 0; j < 4; j++)
                    w[j] = *(const ulonglong2*)(W2t + (oc + 16 * j) * 68 + k);
                #pragma unroll
                for (int i = 0; i < 4; i++) {
                    ulonglong2 x = *(const ulonglong2*)(H1e + (eg * 4 + i) * 68 + k);
                    #pragma unroll
                    for (int j = 0; j < 4; j++) {
                        ffma2(acc[i][j], x.x, w[j].x);
                        ffma2(acc[i][j], x.y, w[j].y);
                    }
                }
            }
            #pragma unroll
            for (int i = 0; i < 4; i++)
                #pragma unroll
                for (int j = 0; j < 4; j++)
                    H2e[(eg * 4 + i) * 68 + oc + 16 * j] = silu_f(f2x_sum(acc[i][j]));
        }
        __syncthreads();

        // ---- P3: scatter C·H2 -> g_hagg ----
        {
            const int oc2 = (tid & 31) * 2;
            const int eg = tid >> 5;
            int cur = dstSh[eg * 8];
            float s0 = 0.f, s1 = 0.f;
            #pragma unroll
            for (int i = 0; i < 8; i++) {
                const int ee = eg * 8 + i;
                int dd2 = dstSh[ee];
                if (dd2 != cur) {
                    atomicAdd(&g_hagg[cur * HID + oc2], s0);
                    atomicAdd(&g_hagg[cur * HID + oc2 + 1], s1);
                    cur = dd2; s0 = s1 = 0.f;
                }
                float c = CS[ee];
                float2 h2 = *(const float2*)(H2e + ee * 68 + oc2);
                s0 += h2.x * c; s1 += h2.y * c;
            }
            atomicAdd(&g_hagg[cur * HID + oc2], s0);
            atomicAdd(&g_hagg[cur * HID + oc2 + 1], s1);
        }

        // ---- P4: gates + in-warp segmented v-reduce (tid < 64) ----
        if (tid < TE) {
            const int ee = tid;
            const int epos = base + ee;
            unsigned long long g2[6];
            #pragma unroll
            for (int j = 0; j < 6; j++) g2[j] = 0ull;
            #pragma unroll 4
            for (int k = 0; k < 64; k += 4) {
                ulonglong2 x = *(const ulonglong2*)(H2e + ee * 68 + k);
                #pragma unroll
                for (int j = 0; j < 6; j++) {
                    ulonglong2 w = *(const ulonglong2*)(W3g + j * 68 + k);
                    ffma2(g2[j], x.x, w.x);
                    ffma2(g2[j], x.y, w.y);
                }
            }
            float a6[6];
            #pragma unroll
            for (int j = 0; j < 6; j++) a6[j] = b3g[j] + f2x_sum(g2[j]);

            const float c = CS[ee];
            const int src = srcSh[ee];
            const int dst = dstSh[ee];
            float rv[3];
            #pragma unroll
            for (int x = 0; x < 3; x++) rv[x] = (epos < EE) ? g_rs[epos * 3 + x] : 0.0f;
            float m[9];
            #pragma unroll
            for (int vi = 0; vi < 3; vi++) {
                const float gv = a6[vi], gr = a6[3 + vi];
                #pragma unroll
                for (int x = 0; x < 3; x++)
                    m[vi * 3 + x] = (g_vbuf[src * 9 + vi * 3 + x] * gv + rv[x] * gr) * c;
            }

            const int l16 = lane & 15;
            bool ok[4];
            #pragma unroll
            for (int s9 = 0; s9 < 4; s9++) {
                int off = 1 << s9;
                int ud = __shfl_up_sync(0xffffffffu, dst, off);
                ok[s9] = (l16 >= off) && (ud == dst);
            }
            int nd = __shfl_down_sync(0xffffffffu, dst, 1);
            const bool tail = (l16 == 15) || (nd != dst);
            #pragma unroll
            for (int col = 0; col < 9; col++) {
                float vv = m[col];
                #pragma unroll
                for (int s9 = 0; s9 < 4; s9++) {
                    float uv = __shfl_up_sync(0xffffffffu, vv, 1 << s9);
                    if (ok[s9]) vv += uv;
                }
                if (tail) atomicAdd(&g_vagg[dst * 9 + col], vv);
            }
        }
    }
}

// ---------------- node kernel: 512 threads, 16 warps/SM ----------------
#define N_W1T 0                          // 64 x 200 = 12800
#define N_W2T (N_W1T + 12800)            // 128 x 68 = 8704
#define N_B2  (N_W2T + 8704)
#define N_BN1 (N_B2 + 128)
#define N_BC  (N_BN1 + 64)
#define N_CT  (N_BC + 64)
#define N_XT  (N_CT + 64)                // 64 x 200 = 12800
#define N_UT  (N_XT + 12800)             // 4352
#define N_TOT (N_UT + 4352)              // 38976 floats = 155904 B

__global__ void __launch_bounds__(512, 1) k_node(
    const float* __restrict__ Wn1, const float* __restrict__ bn1,
    const float* __restrict__ Wn2, const float* __restrict__ bn2,
    const float* __restrict__ Wc, const float* __restrict__ bc)
{
    extern __shared__ float sm[];
    float* W1t = sm + N_W1T;
    float* W2t = sm + N_W2T;
    float* b2s = sm + N_B2;
    float* bn1s = sm + N_BN1;
    float* bcs = sm + N_BC;
    float* CT  = sm + N_CT;
    float* Xt  = sm + N_XT;
    float* Ut  = sm + N_UT;

    const int tid = threadIdx.x;
    for (int i = tid; i < 64 * 128; i += 512) {
        int k = i >> 6, o = i & 63;
        W1t[o * 200 + k] = Wn1[k * 64 + o];
    }
    for (int i = tid; i < 64 * 64; i += 512) {
        int k = i >> 6, o = i & 63;
        W1t[o * 200 + 128 + k] = Wc[k * 64 + o];
    }
    for (int i = tid; i < 128 * 64; i += 512) {
        int k = i >> 7, o = i & 127;
        W2t[o * 68 + k] = Wn2[k * 128 + o];
    }
    if (tid < 64) { bn1s[tid] = bn1[tid]; bcs[tid] = bc[tid]; }
    if (tid < 128) b2s[tid] = bn2[tid];
    __syncthreads();

    const int wid = tid >> 5, lane = tid & 31;

    for (int tile = blockIdx.x; tile < NT_N; tile += gridDim.x) {
        const int base = tile * TN;
        const int nNd = min(TN, NN - base);

        for (int ii = wid; ii < TN; ii += 16) {
            const int n = base + ii;
            const bool valid = (ii < nNd);
            const float4* sp = (const float4*)&g_sbuf[(valid ? n : 0) * SD];
            float4 xs = sp[lane];
            if (!valid) xs = make_float4(0, 0, 0, 0);
            *(float4*)(Xt + ii * 200 + lane * 4) = xs;
            if (lane < 16) {
                float4* hp = (float4*)&g_hagg[(valid ? n : 0) * HID];
                float4 xh = hp[lane];
                if (!valid) xh = make_float4(0, 0, 0, 0);
                *(float4*)(Xt + ii * 200 + 128 + lane * 4) = xh;
                if (valid) hp[lane] = make_float4(0, 0, 0, 0);
            }
        }
        if (tid < 64) CT[tid] = (tid < nNd) ? g_cntC[base + tid] : 0.0f;

        // fused v update
        for (int idx = tid; idx < TN * 9; idx += 512) {
            const int nn = base + idx / 9;
            if (idx / 9 < nNd) {
                const int col = idx % 9;
                float va = g_vagg[nn * 9 + col];
                float nv = g_vbuf[nn * 9 + col] + va * g_icnt[nn];
                g_vbuf[nn * 9 + col] = nv;
                g_vagg[nn * 9 + col] = 0.0f;
            }
        }
        __syncthreads();

        // GEMM1: Ut = silu(s@Wn1a + hagg@Wc + cntC*bc + bn1)   (k = 192)
        {
            const int oc = tid & 15;
            const int eg = tid >> 4;   // 0..31, 2 nodes each
            unsigned long long acc[2][4];
            #pragma unroll
            for (int i = 0; i < 2; i++) {
                float ci = CT[eg * 2 + i];
                #pragma unroll
                for (int j = 0; j < 4; j++)
                    acc[i][j] = packlo(bn1s[oc + 16 * j] + ci * bcs[oc + 16 * j]);
            }
            #pragma unroll 2
            for (int k = 0; k < 192; k += 4) {
                ulonglong2 w[4];
                #pragma unroll
                for (int j = 0; j < 4; j++)
                    w[j] = *(const ulonglong2*)(W1t + (oc + 16 * j) * 200 + k);
                #pragma unroll
                for (int i = 0; i < 2; i++) {
                    ulonglong2 x = *(const ulonglong2*)(Xt + (eg * 2 + i) * 200 + k);
                    #pragma unroll
                    for (int j = 0; j < 4; j++) {
                        ffma2(acc[i][j], x.x, w[j].x);
                        ffma2(acc[i][j], x.y, w[j].y);
                    }
                }
            }
            #pragma unroll
            for (int i = 0; i < 2; i++)
                #pragma unroll
                for (int j = 0; j < 4; j++)
                    Ut[(eg * 2 + i) * 68 + oc + 16 * j] = silu_f(f2x_sum(acc[i][j]));
        }
        __syncthreads();

        // GEMM2: s += Ut @ Wn2 + bn2   (4 nodes x 4 cols / thread)
        {
            const int oc = tid & 31;
            const int eg = tid >> 5;   // 0..15, 4 nodes each
            unsigned long long acc[4][4];
            #pragma unroll
            for (int i = 0; i < 4; i++)
                #pragma unroll
                for (int j = 0; j < 4; j++) acc[i][j] = packlo(b2s[oc + 32 * j]);
            #pragma unroll 4
            for (int k = 0; k < 64; k += 4) {
                ulonglong2 w[4];
                #pragma unroll
                for (int j = 0; j < 4; j++)
                    w[j] = *(const ulonglong2*)(W2t + (oc + 32 * j) * 68 + k);
                #pragma unroll
                for (int i = 0; i < 4; i++) {
                    ulonglong2 x = *(const ulonglong2*)(Ut + (eg * 4 + i) * 68 + k);
                    #pragma unroll
                    for (int j = 0; j < 4; j++) {
                        ffma2(acc[i][j], x.x, w[j].x);
                        ffma2(acc[i][j], x.y, w[j].y);
                    }
                }
            }
            #pragma unroll
            for (int i = 0; i < 4; i++) {
                const int n = base + eg * 4 + i;
                if (eg * 4 + i < nNd) {
                    #pragma unroll
                    for (int j = 0; j < 4; j++)
                        g_sbuf[n * SD + oc + 32 * j] += f2x_sum(acc[i][j]);
                }
            }
        }
        __syncthreads();
    }
}

// ---------------- host launch ----------------
extern "C" void kernel_launch(void* const* d_in, const int* in_sizes, int n_in,
                              void* d_out, int out_size) {
    const float* s   = (const float*)d_in[0];
    const float* v   = (const float*)d_in[1];
    const int*   ei  = (const int*)d_in[2];
    const float* d   = (const float*)d_in[3];
    const float* r   = (const float*)d_in[4];
    const float* W1  = (const float*)d_in[5];
    const float* b1  = (const float*)d_in[6];
    const float* W2  = (const float*)d_in[7];
    const float* b2  = (const float*)d_in[8];
    const float* W3  = (const float*)d_in[9];
    const float* b3  = (const float*)d_in[10];
    const float* Wn1 = (const float*)d_in[11];
    const float* bn1 = (const float*)d_in[12];
    const float* Wn2 = (const float*)d_in[13];
    const float* bn2 = (const float*)d_in[14];
    float* out = (float*)d_out;

    const int psm = P_TOT * 4;
    const int esm = E_TOT * 4;
    const int nsm = N_TOT * 4;
    cudaFuncSetAttribute(k_permproj, cudaFuncAttributeMaxDynamicSharedMemorySize, psm);
    cudaFuncSetAttribute(k_proj, cudaFuncAttributeMaxDynamicSharedMemorySize, psm);
    cudaFuncSetAttribute(k_edge, cudaFuncAttributeMaxDynamicSharedMemorySize, esm);
    cudaFuncSetAttribute(k_node, cudaFuncAttributeMaxDynamicSharedMemorySize, nsm);

    float* d_Wc; cudaGetSymbolAddress((void**)&d_Wc, g_Wc);
    float* d_bc; cudaGetSymbolAddress((void**)&d_bc, g_bc);

    k_init<<<1024, 256>>>(s, v, ei);                        // 1
    k_scan<<<1, 1024>>>();                                  // 2
    k_permproj<<<NT_N + PERMB, 256, psm>>>(ei, d, r, W1);   // 3

    for (int l = 0; l < DEPTH; l++) {
        k_edge<<<456, 256, esm>>>(W1 + l * 257 * 64, b1 + l * 64,   // 4 (l=0) -> ncu
                                  W2 + l * 64 * 64, b2 + l * 64,
                                  W3 + l * 64 * 134, b3 + l * 134);
        if (l == 0) k_wc<<<DEPTH, 256>>>(W3, b3, Wn1);
        k_node<<<152, 512, nsm>>>(Wn1 + l * 256 * 64, bn1 + l * 64,
                                  Wn2 + l * 64 * 128, bn2 + l * 128,
                                  d_Wc + l * 4096, d_bc + l * 64);
        if (l < DEPTH - 1)
            k_proj<<<NT_N, 256, psm>>>(W1 + (l + 1) * 257 * 64);
    }
    k_out<<<1024, 256>>>(out);
}

// round 16
// speedup vs baseline: 1.0287x; 1.0287x over previous
#include <cuda_runtime.h>

#define NN 50000
#define EE 500000
#define SD 128
#define HID 64
#define DEPTH 4
#define CUTF 5.0f
#define PI_F 3.14159265358979f

#define TE 64
#define NT_E ((EE + TE - 1) / TE)
#define TN 64
#define NT_N ((NN + TN - 1) / TN)

// ---------------- device scratch ----------------
__device__ float g_sbuf[NN * SD];
__device__ float g_vbuf[NN * 9];
__device__ float g_hagg[NN * HID];
__device__ float g_vagg[NN * 9];
__device__ float g_Pa[NN * HID];
__device__ float g_Pb[NN * HID];
__device__ float g_icnt[NN];
__device__ float g_cntC[NN];
__device__ int   g_cnti[NN];
__device__ int   g_cur[NN];
__device__ int   g_dstS[EE];
__device__ int   g_srcS[EE];
__device__ float g_Cs[EE];
__device__ float g_dsrt[EE];
__device__ float g_rs[EE * 3];
__device__ float g_Wc[DEPTH * 64 * 64];
__device__ float g_bc[DEPTH * 64];

__device__ __forceinline__ float silu_f(float x) {
    return x / (1.0f + __expf(-x));
}

__device__ __forceinline__ void ffma2(unsigned long long& acc,
                                      unsigned long long a, unsigned long long b) {
    asm("fma.rn.f32x2 %0, %1, %2, %0;" : "+l"(acc) : "l"(a), "l"(b));
}
__device__ __forceinline__ unsigned long long packlo(float x) {
    return (unsigned long long)__float_as_uint(x);
}
__device__ __forceinline__ float f2x_sum(unsigned long long a) {
    float lo = __int_as_float((unsigned)(a & 0xffffffffull));
    float hi = __int_as_float((unsigned)(a >> 32));
    return lo + hi;
}

// ---------------- small kernels ----------------
__global__ void k_init(const float* __restrict__ s, const float* __restrict__ v) {
    int i = blockIdx.x * blockDim.x + threadIdx.x;
    int stride = gridDim.x * blockDim.x;
    for (int j = i; j < NN * SD; j += stride) g_sbuf[j] = s[j];
    for (int j = i; j < NN * 9; j += stride) g_vbuf[j] = v[j];
    for (int j = i; j < NN; j += stride) { g_cnti[j] = 0; g_cntC[j] = 0.0f; }
}

__global__ void k_cnt(const int* __restrict__ ei) {
    int e = blockIdx.x * blockDim.x + threadIdx.x;
    if (e < EE) atomicAdd(&g_cnti[ei[e]], 1);
}

__global__ void k_scan() {
    __shared__ int sh[1024];
    __shared__ int carry;
    int tid = threadIdx.x;
    if (tid == 0) carry = 0;
    __syncthreads();
    for (int base = 0; base < NN; base += 1024) {
        int i = base + tid;
        int x = (i < NN) ? g_cnti[i] : 0;
        sh[tid] = x;
        __syncthreads();
        for (int off = 1; off < 1024; off <<= 1) {
            int t = (tid >= off) ? sh[tid - off] : 0;
            __syncthreads();
            sh[tid] += t;
            __syncthreads();
        }
        if (i < NN) {
            g_cur[i] = carry + sh[tid] - x;
            g_icnt[i] = 1.0f / fmaxf((float)x, 1.0f);
        }
        __syncthreads();
        if (tid == 1023) carry += sh[1023];
        __syncthreads();
    }
}

__global__ void k_perm(const int* __restrict__ ei, const float* __restrict__ d,
                       const float* __restrict__ r) {
    int e = blockIdx.x * blockDim.x + threadIdx.x;
    if (e < EE) {
        int dst = ei[e];
        int pos = atomicAdd(&g_cur[dst], 1);
        g_dstS[pos] = dst;
        g_srcS[pos] = ei[EE + e];
        float dd = d[e];
        g_dsrt[pos] = dd;
        float c = (dd < CUTF) ? 0.5f * (cosf(PI_F * dd / CUTF) + 1.0f) : 0.0f;
        g_Cs[pos] = c;
        atomicAdd(&g_cntC[dst], c);
        g_rs[pos * 3 + 0] = r[e * 3 + 0];
        g_rs[pos * 3 + 1] = r[e * 3 + 1];
        g_rs[pos * 3 + 2] = r[e * 3 + 2];
    }
}

__global__ void k_zero() {
    int i = blockIdx.x * blockDim.x + threadIdx.x;
    int stride = gridDim.x * blockDim.x;
    for (int j = i; j < NN * HID; j += stride) g_hagg[j] = 0.0f;
    for (int j = i; j < NN * 9; j += stride) g_vagg[j] = 0.0f;
}

// Wc[l] = W3s[l] @ Wn1b[l] ; bc[l] = b3s[l] @ Wn1b[l]
__global__ void k_wc(const float* __restrict__ W3, const float* __restrict__ b3,
                     const float* __restrict__ Wn1) {
    const int l = blockIdx.x;
    const float* w3 = W3 + l * 64 * 134;
    const float* wn1b = Wn1 + l * 256 * 64 + 128 * 64;
    const float* b3l = b3 + l * 134;
    const int tid = threadIdx.x;
    const int o = tid & 63;
    for (int h = tid >> 6; h < 64; h += 4) {
        float acc = 0.0f;
        for (int m = 0; m < 128; m++)
            acc += w3[h * 134 + m] * wn1b[m * 64 + o];
        g_Wc[l * 4096 + h * 64 + o] = acc;
    }
    if (tid < 64) {
        float acc = 0.0f;
        for (int m = 0; m < 128; m++) acc += b3l[m] * wn1b[m * 64 + tid];
        g_bc[l * 64 + tid] = acc;
    }
}

__global__ void k_out(float* __restrict__ out) {
    int i = blockIdx.x * blockDim.x + threadIdx.x;
    int stride = gridDim.x * blockDim.x;
    for (int j = i; j < NN * SD; j += stride) out[j] = g_sbuf[j];
    for (int j = i; j < NN * 9; j += stride) out[NN * SD + j] = g_vbuf[j];
}

// ---------------- projection ----------------
#define P_W 0
#define P_X (P_W + 128 * 132)
#define P_TOT (P_X + 64 * 132)

__global__ void __launch_bounds__(256, 2) k_proj(const float* __restrict__ W1) {
    extern __shared__ float sm[];
    float* Ws = sm + P_W;
    float* Xt = sm + P_X;

    const int tid = threadIdx.x;
    for (int i = tid; i < 128 * 128; i += 256) {
        int k = i >> 7, o = i & 127;
        float w = (o < 64) ? W1[k * 64 + o] : W1[(128 + k) * 64 + (o - 64)];
        Ws[o * 132 + k] = w;
    }

    const int wid = tid >> 5, lane = tid & 31;
    const int base = blockIdx.x * TN;
    const int nNd = min(TN, NN - base);

    for (int ii = wid; ii < TN; ii += 8) {
        const int n = base + ii;
        const bool valid = (ii < nNd);
        const float4* sp = (const float4*)&g_sbuf[(valid ? n : 0) * SD];
        float4 x = sp[lane];
        if (!valid) x = make_float4(0.f, 0.f, 0.f, 0.f);
        *(float4*)(Xt + ii * 132 + lane * 4) = x;
    }
    __syncthreads();

    const int oc = tid & 31;
    const int eg = tid >> 5;
    unsigned long long acc[8][4];
    #pragma unroll
    for (int i = 0; i < 8; i++)
        #pragma unroll
        for (int j = 0; j < 4; j++) acc[i][j] = 0ull;

    #pragma unroll 2
    for (int k = 0; k < 128; k += 4) {
        ulonglong2 w[4];
        #pragma unroll
        for (int j = 0; j < 4; j++)
            w[j] = *(const ulonglong2*)(Ws + (oc + 32 * j) * 132 + k);
        #pragma unroll
        for (int i = 0; i < 8; i++) {
            ulonglong2 x = *(const ulonglong2*)(Xt + (eg * 8 + i) * 132 + k);
            #pragma unroll
            for (int j = 0; j < 4; j++) {
                ffma2(acc[i][j], x.x, w[j].x);
                ffma2(acc[i][j], x.y, w[j].y);
            }
        }
    }
    #pragma unroll
    for (int i = 0; i < 8; i++) {
        const int n = base + eg * 8 + i;
        if (eg * 8 + i < nNd) {
            #pragma unroll
            for (int j = 0; j < 4; j++) {
                const int o = oc + 32 * j;
                float val = f2x_sum(acc[i][j]);
                if (o < 64) g_Pa[n * HID + o] = val;
                else        g_Pb[n * HID + (o - 64)] = val;
            }
        }
    }
}

// ---------------- edge kernel: H1 in-place in PbN, 4 blocks/SM ----------------
#define E_W2T 0                         // 4352
#define E_W3G (E_W2T + 4352)            // 416
#define E_B1  (E_W3G + 416)             // 64
#define E_B2  (E_B1 + 64)               // 64
#define E_B3G (E_B2 + 64)               // 16
#define E_W1D (E_B3G + 16)              // 64
#define E_H2  (E_W1D + 64)              // 4352
#define E_CS  (E_H2 + 4352)             // 64
#define E_DS  (E_CS + 64)               // 64
#define E_SS  (E_DS + 64)               // 64
#define E_PBN (E_SS + 64)               // 4096  (byte off 38080, 16B aligned)
#define E_TOT (E_PBN + 4096)            // 13616 floats = 54464 B -> 4 blocks/SM

__device__ __forceinline__ void prefetch_pb(float* PbN, int ntile, int tid) {
    if (ntile < NT_E) {
        const int base2 = ntile * TE;
        const int e = tid >> 2;
        const int epos = min(base2 + e, EE - 1);
        const int se = g_srcS[epos];
        const int f0 = (tid & 3) * 16;
        const float* gp = &g_Pb[se * HID + f0];
        unsigned saddr = (unsigned)__cvta_generic_to_shared(PbN + e * 64 + f0);
        #pragma unroll
        for (int c = 0; c < 4; c++)
            asm volatile("cp.async.cg.shared.global [%0], [%1], 16;"
                         :: "r"(saddr + c * 16), "l"(gp + c * 4) : "memory");
    }
    asm volatile("cp.async.commit_group;" ::: "memory");
}

__global__ void __launch_bounds__(256, 4) k_edge(
    const float* __restrict__ W1, const float* __restrict__ b1,
    const float* __restrict__ W2, const float* __restrict__ b2,
    const float* __restrict__ W3, const float* __restrict__ b3)
{
    extern __shared__ float sm[];
    float* W2t = sm + E_W2T;
    float* W3g = sm + E_W3G;
    float* b1s = sm + E_B1;
    float* b2s = sm + E_B2;
    float* b3g = sm + E_B3G;
    float* w1d = sm + E_W1D;
    float* H2e = sm + E_H2;
    float* CS  = sm + E_CS;
    int*   dstSh = (int*)(sm + E_DS);
    int*   srcSh = (int*)(sm + E_SS);
    float* PbN = sm + E_PBN;   // doubles as H1 [64 e][64 k] after P1

    const int tid = threadIdx.x;

    for (int i = tid; i < 64 * 64; i += 256) {
        int k = i >> 6, o = i & 63;
        W2t[o * 68 + k] = W2[k * 64 + o];
    }
    for (int i = tid; i < 6 * 64; i += 256) {
        int o = i % 6, k = i / 6;
        W3g[o * 68 + k] = W3[k * 134 + 128 + o];
    }
    if (tid < 64) {
        b1s[tid] = b1[tid];
        b2s[tid] = b2[tid];
        w1d[tid] = W1[256 * 64 + tid];
    }
    if (tid < 6) b3g[tid] = b3[128 + tid];

    const int wid = tid >> 5, lane = tid & 31;

    prefetch_pb(PbN, blockIdx.x, tid);

    for (int tile = blockIdx.x; tile < NT_E; tile += gridDim.x) {
        const int base = tile * TE;
        const int nE = min(TE, EE - base);

        asm volatile("cp.async.wait_group 0;" ::: "memory");
        __syncthreads();   // PbN staged; covers prior epilogue + weight staging

        // ---- P1: gather Pa + staged Pb -> silu -> H1 (in place, stride 64) ----
        #pragma unroll 2
        for (int i = 0; i < 8; i++) {
            const int ee = wid * 8 + i;
            const int epos = base + ee;
            const bool valid = (ee < nE);
            int dst = 0, src = 0;
            float dd = 0.0f;
            if (valid) { dst = g_dstS[epos]; src = g_srcS[epos]; dd = g_dsrt[epos]; }
            const float2 a = ((const float2*)&g_Pa[dst * HID])[lane];
            const float2 b = ((const float2*)(PbN + ee * 64))[lane];
            const int k0 = lane * 2;
            float h0 = a.x + b.x + dd * w1d[k0] + b1s[k0];
            float h1 = a.y + b.y + dd * w1d[k0 + 1] + b1s[k0 + 1];
            float2 hv;
            hv.x = valid ? silu_f(h0) : 0.0f;
            hv.y = valid ? silu_f(h1) : 0.0f;
            *(float2*)(PbN + ee * 64 + k0) = hv;   // in-place: own slot
            if (lane == 0) {
                CS[ee] = valid ? g_Cs[epos] : 0.0f;
                dstSh[ee] = dst; srcSh[ee] = src;
            }
        }
        __syncthreads();

        // ---- P2: GEMM2 (reads H1 = PbN, stride 64) -> H2e ----
        {
            const int oc = tid & 15;
            const int eg = tid >> 4;
            unsigned long long acc[4][4];
            #pragma unroll
            for (int i = 0; i < 4; i++)
                #pragma unroll
                for (int j = 0; j < 4; j++) acc[i][j] = packlo(b2s[oc + 16 * j]);
            #pragma unroll 4
            for (int k = 0; k < 64; k += 4) {
                ulonglong2 w[4];
                #pragma unroll
                for (int j = 0; j < 4; j++)
                    w[j] = *(const ulonglong2*)(W2t + (oc + 16 * j) * 68 + k);
                #pragma unroll
                for (int i = 0; i < 4; i++) {
                    ulonglong2 x = *(const ulonglong2*)(PbN + (eg * 4 + i) * 64 + k);
                    #pragma unroll
                    for (int j = 0; j < 4; j++) {
                        ffma2(acc[i][j], x.x, w[j].x);
                        ffma2(acc[i][j], x.y, w[j].y);
                    }
                }
            }
            #pragma unroll
            for (int i = 0; i < 4; i++)
                #pragma unroll
                for (int j = 0; j < 4; j++)
                    H2e[(eg * 4 + i) * 68 + oc + 16 * j] = silu_f(f2x_sum(acc[i][j]));
        }
        __syncthreads();   // H1 dead; safe to overwrite PbN

        // issue next tile's Pb prefetch — overlaps P3/P4
        prefetch_pb(PbN, tile + gridDim.x, tid);

        // ---- P3: scatter C·H2 -> g_hagg (run-reduced) ----
        {
            const int oc2 = (tid & 31) * 2;
            const int eg = tid >> 5;
            int cur = dstSh[eg * 8];
            float s0 = 0.f, s1 = 0.f;
            #pragma unroll
            for (int i = 0; i < 8; i++) {
                const int ee = eg * 8 + i;
                int dd2 = dstSh[ee];
                if (dd2 != cur) {
                    atomicAdd(&g_hagg[cur * HID + oc2], s0);
                    atomicAdd(&g_hagg[cur * HID + oc2 + 1], s1);
                    cur = dd2; s0 = s1 = 0.f;
                }
                float c = CS[ee];
                float2 h2 = *(const float2*)(H2e + ee * 68 + oc2);
                s0 += h2.x * c; s1 += h2.y * c;
            }
            atomicAdd(&g_hagg[cur * HID + oc2], s0);
            atomicAdd(&g_hagg[cur * HID + oc2 + 1], s1);
        }

        // ---- P4: gates + in-warp segmented v-reduce (tid < 64) ----
        if (tid < TE) {
            const int ee = tid;
            const int epos = base + ee;
            unsigned long long g2[6];
            #pragma unroll
            for (int j = 0; j < 6; j++) g2[j] = 0ull;
            #pragma unroll 4
            for (int k = 0; k < 64; k += 4) {
                ulonglong2 x = *(const ulonglong2*)(H2e + ee * 68 + k);
                #pragma unroll
                for (int j = 0; j < 6; j++) {
                    ulonglong2 w = *(const ulonglong2*)(W3g + j * 68 + k);
                    ffma2(g2[j], x.x, w.x);
                    ffma2(g2[j], x.y, w.y);
                }
            }
            float a6[6];
            #pragma unroll
            for (int j = 0; j < 6; j++) a6[j] = b3g[j] + f2x_sum(g2[j]);

            const float c = CS[ee];
            const int src = srcSh[ee];
            const int dst = dstSh[ee];
            float rv[3];
            #pragma unroll
            for (int x = 0; x < 3; x++) rv[x] = (epos < EE) ? g_rs[epos * 3 + x] : 0.0f;
            float m[9];
            #pragma unroll
            for (int vi = 0; vi < 3; vi++) {
                const float gv = a6[vi], gr = a6[3 + vi];
                #pragma unroll
                for (int x = 0; x < 3; x++)
                    m[vi * 3 + x] = (g_vbuf[src * 9 + vi * 3 + x] * gv + rv[x] * gr) * c;
            }

            const int l16 = lane & 15;
            bool ok[4];
            #pragma unroll
            for (int s9 = 0; s9 < 4; s9++) {
                int off = 1 << s9;
                int ud = __shfl_up_sync(0xffffffffu, dst, off);
                ok[s9] = (l16 >= off) && (ud == dst);
            }
            int nd = __shfl_down_sync(0xffffffffu, dst, 1);
            const bool tail = (l16 == 15) || (nd != dst);
            #pragma unroll
            for (int col = 0; col < 9; col++) {
                float vv = m[col];
                #pragma unroll
                for (int s9 = 0; s9 < 4; s9++) {
                    float uv = __shfl_up_sync(0xffffffffu, vv, 1 << s9);
                    if (ok[s9]) vv += uv;
                }
                if (tail) atomicAdd(&g_vagg[dst * 9 + col], vv);
            }
        }
        // loop-top wait+barrier covers P3/P4 completion before smem reuse
    }
}

// ---------------- node kernel (R10 winner: 256 threads, k=192 GEMM1) ----------------
#define N_W1T 0
#define N_W2T (N_W1T + 12800)
#define N_B2  (N_W2T + 8704)
#define N_BN1 (N_B2 + 128)
#define N_BC  (N_BN1 + 64)
#define N_CT  (N_BC + 64)
#define N_XT  (N_CT + 64)
#define N_UT  (N_XT + 12800)
#define N_TOT (N_UT + 4352)              // 38976 floats = 155904 B

__global__ void __launch_bounds__(256, 1) k_node(
    const float* __restrict__ Wn1, const float* __restrict__ bn1,
    const float* __restrict__ Wn2, const float* __restrict__ bn2,
    const float* __restrict__ Wc, const float* __restrict__ bc)
{
    extern __shared__ float sm[];
    float* W1t = sm + N_W1T;
    float* W2t = sm + N_W2T;
    float* b2s = sm + N_B2;
    float* bn1s = sm + N_BN1;
    float* bcs = sm + N_BC;
    float* CT  = sm + N_CT;
    float* Xt  = sm + N_XT;
    float* Ut  = sm + N_UT;

    const int tid = threadIdx.x;
    for (int i = tid; i < 64 * 128; i += 256) {
        int k = i >> 6, o = i & 63;
        W1t[o * 200 + k] = Wn1[k * 64 + o];
    }
    for (int i = tid; i < 64 * 64; i += 256) {
        int k = i >> 6, o = i & 63;
        W1t[o * 200 + 128 + k] = Wc[k * 64 + o];
    }
    for (int i = tid; i < 128 * 64; i += 256) {
        int k = i >> 7, o = i & 127;
        W2t[o * 68 + k] = Wn2[k * 128 + o];
    }
    if (tid < 64) { bn1s[tid] = bn1[tid]; bcs[tid] = bc[tid]; }
    if (tid < 128) b2s[tid] = bn2[tid];
    __syncthreads();

    const int wid = tid >> 5, lane = tid & 31;

    for (int tile = blockIdx.x; tile < NT_N; tile += gridDim.x) {
        const int base = tile * TN;
        const int nNd = min(TN, NN - base);

        for (int ii = wid; ii < TN; ii += 8) {
            const int n = base + ii;
            const bool valid = (ii < nNd);
            const float4* sp = (const float4*)&g_sbuf[(valid ? n : 0) * SD];
            float4 xs = sp[lane];
            if (!valid) xs = make_float4(0, 0, 0, 0);
            *(float4*)(Xt + ii * 200 + lane * 4) = xs;
            if (lane < 16) {
                float4* hp = (float4*)&g_hagg[(valid ? n : 0) * HID];
                float4 xh = hp[lane];
                if (!valid) xh = make_float4(0, 0, 0, 0);
                *(float4*)(Xt + ii * 200 + 128 + lane * 4) = xh;
                if (valid) hp[lane] = make_float4(0, 0, 0, 0);
            }
        }
        if (tid < 64) CT[tid] = (tid < nNd) ? g_cntC[base + tid] : 0.0f;

        for (int idx = tid; idx < TN * 9; idx += 256) {
            const int nn = base + idx / 9;
            if (idx / 9 < nNd) {
                const int col = idx % 9;
                float va = g_vagg[nn * 9 + col];
                float nv = g_vbuf[nn * 9 + col] + va * g_icnt[nn];
                g_vbuf[nn * 9 + col] = nv;
                g_vagg[nn * 9 + col] = 0.0f;
            }
        }
        __syncthreads();

        // GEMM1: Ut = silu(s@Wn1a + hagg@Wc + cntC*bc + bn1)   (k = 192)
        {
            const int oc = tid & 15;
            const int eg = tid >> 4;
            unsigned long long acc[4][4];
            #pragma unroll
            for (int i = 0; i < 4; i++) {
                float ci = CT[eg * 4 + i];
                #pragma unroll
                for (int j = 0; j < 4; j++)
                    acc[i][j] = packlo(bn1s[oc + 16 * j] + ci * bcs[oc + 16 * j]);
            }
            #pragma unroll 2
            for (int k = 0; k < 192; k += 4) {
                ulonglong2 w[4];
                #pragma unroll
                for (int j = 0; j < 4; j++)
                    w[j] = *(const ulonglong2*)(W1t + (oc + 16 * j) * 200 + k);
                #pragma unroll
                for (int i = 0; i < 4; i++) {
                    ulonglong2 x = *(const ulonglong2*)(Xt + (eg * 4 + i) * 200 + k);
                    #pragma unroll
                    for (int j = 0; j < 4; j++) {
                        ffma2(acc[i][j], x.x, w[j].x);
                        ffma2(acc[i][j], x.y, w[j].y);
                    }
                }
            }
            #pragma unroll
            for (int i = 0; i < 4; i++)
                #pragma unroll
                for (int j = 0; j < 4; j++)
                    Ut[(eg * 4 + i) * 68 + oc + 16 * j] = silu_f(f2x_sum(acc[i][j]));
        }
        __syncthreads();

        // GEMM2: s += Ut @ Wn2 + bn2
        {
            const int oc = tid & 31;
            const int eg = tid >> 5;
            unsigned long long acc[8][4];
            #pragma unroll
            for (int i = 0; i < 8; i++)
                #pragma unroll
                for (int j = 0; j < 4; j++) acc[i][j] = packlo(b2s[oc + 32 * j]);
            #pragma unroll 4
            for (int k = 0; k < 64; k += 4) {
                ulonglong2 w[4];
                #pragma unroll
                for (int j = 0; j < 4; j++)
                    w[j] = *(const ulonglong2*)(W2t + (oc + 32 * j) * 68 + k);
                #pragma unroll
                for (int i = 0; i < 8; i++) {
                    ulonglong2 x = *(const ulonglong2*)(Ut + (eg * 8 + i) * 68 + k);
                    #pragma unroll
                    for (int j = 0; j < 4; j++) {
                        ffma2(acc[i][j], x.x, w[j].x);
                        ffma2(acc[i][j], x.y, w[j].y);
                    }
                }
            }
            #pragma unroll
            for (int i = 0; i < 8; i++) {
                const int n = base + eg * 8 + i;
                if (eg * 8 + i < nNd) {
                    #pragma unroll
                    for (int j = 0; j < 4; j++)
                        g_sbuf[n * SD + oc + 32 * j] += f2x_sum(acc[i][j]);
                }
            }
        }
        __syncthreads();
    }
}

// ---------------- host launch (R10 order) ----------------
extern "C" void kernel_launch(void* const* d_in, const int* in_sizes, int n_in,
                              void* d_out, int out_size) {
    const float* s   = (const float*)d_in[0];
    const float* v   = (const float*)d_in[1];
    const int*   ei  = (const int*)d_in[2];
    const float* d   = (const float*)d_in[3];
    const float* r   = (const float*)d_in[4];
    const float* W1  = (const float*)d_in[5];
    const float* b1  = (const float*)d_in[6];
    const float* W2  = (const float*)d_in[7];
    const float* b2  = (const float*)d_in[8];
    const float* W3  = (const float*)d_in[9];
    const float* b3  = (const float*)d_in[10];
    const float* Wn1 = (const float*)d_in[11];
    const float* bn1 = (const float*)d_in[12];
    const float* Wn2 = (const float*)d_in[13];
    const float* bn2 = (const float*)d_in[14];
    float* out = (float*)d_out;

    const int psm = P_TOT * 4;
    const int esm = E_TOT * 4;
    const int nsm = N_TOT * 4;
    cudaFuncSetAttribute(k_proj, cudaFuncAttributeMaxDynamicSharedMemorySize, psm);
    cudaFuncSetAttribute(k_edge, cudaFuncAttributeMaxDynamicSharedMemorySize, esm);
    cudaFuncSetAttribute(k_node, cudaFuncAttributeMaxDynamicSharedMemorySize, nsm);

    float* d_Wc; cudaGetSymbolAddress((void**)&d_Wc, g_Wc);
    float* d_bc; cudaGetSymbolAddress((void**)&d_bc, g_bc);

    k_init<<<1024, 256>>>(s, v);
    k_cnt<<<(EE + 255) / 256, 256>>>(ei);
    k_scan<<<1, 1024>>>();
    k_perm<<<(EE + 255) / 256, 256>>>(ei, d, r);
    k_zero<<<1024, 256>>>();
    k_wc<<<DEPTH, 256>>>(W3, b3, Wn1);

    for (int l = 0; l < DEPTH; l++) {
        k_proj<<<NT_N, 256, psm>>>(W1 + l * 257 * 64);
        k_edge<<<608, 256, esm>>>(W1 + l * 257 * 64, b1 + l * 64,
                                  W2 + l * 64 * 64, b2 + l * 64,
                                  W3 + l * 64 * 134, b3 + l * 134);
        k_node<<<152, 256, nsm>>>(Wn1 + l * 256 * 64, bn1 + l * 64,
                                  Wn2 + l * 64 * 128, bn2 + l * 128,
                                  d_Wc + l * 4096, d_bc + l * 64);
    }
    k_out<<<1024, 256>>>(out);
}

// round 17
// speedup vs baseline: 1.0635x; 1.0338x over previous
#include <cuda_runtime.h>

#define NN 50000
#define EE 500000
#define SD 128
#define HID 64
#define DEPTH 4
#define CUTF 5.0f
#define PI_F 3.14159265358979f

#define TE 64
#define NT_E ((EE + TE - 1) / TE)
#define TN 64
#define NT_N ((NN + TN - 1) / TN)

// ---------------- device scratch ----------------
__device__ float g_sbuf[NN * SD];
__device__ float g_vbuf[NN * 9];
__device__ float g_hagg[NN * HID];
__device__ float g_vagg[NN * 9];
__device__ float g_Pa[NN * HID];
__device__ float g_Pb[NN * HID];
__device__ float g_icnt[NN];
__device__ float g_cntC[NN];
__device__ int   g_cnti[NN];
__device__ int   g_cur[NN];
__device__ int   g_dstS[EE];
__device__ int   g_srcS[EE];
__device__ float g_Cs[EE];
__device__ float g_dsrt[EE];
__device__ float g_rs[EE * 3];
__device__ float g_Wc[DEPTH * 64 * 64];
__device__ float g_bc[DEPTH * 64];

__device__ __forceinline__ float silu_f(float x) {
    return x / (1.0f + __expf(-x));
}

__device__ __forceinline__ void ffma2(unsigned long long& acc,
                                      unsigned long long a, unsigned long long b) {
    asm("fma.rn.f32x2 %0, %1, %2, %0;" : "+l"(acc) : "l"(a), "l"(b));
}
__device__ __forceinline__ unsigned long long packlo(float x) {
    return (unsigned long long)__float_as_uint(x);
}
__device__ __forceinline__ float f2x_sum(unsigned long long a) {
    float lo = __int_as_float((unsigned)(a & 0xffffffffull));
    float hi = __int_as_float((unsigned)(a >> 32));
    return lo + hi;
}

// ---------------- launch 1: pure zero init ----------------
__global__ void k_init() {
    int i = blockIdx.x * blockDim.x + threadIdx.x;
    int stride = gridDim.x * blockDim.x;
    for (int j = i; j < NN * HID; j += stride) g_hagg[j] = 0.0f;
    for (int j = i; j < NN * 9; j += stride) g_vagg[j] = 0.0f;
    for (int j = i; j < NN; j += stride) { g_cnti[j] = 0; g_cntC[j] = 0.0f; }
}

__global__ void k_cnt(const int* __restrict__ ei) {
    int e = blockIdx.x * blockDim.x + threadIdx.x;
    if (e < EE) atomicAdd(&g_cnti[ei[e]], 1);
}

// warp-shuffle scan: 3 barriers per 1024-chunk, carry in registers
__global__ void k_scan() {
    __shared__ int wsum[32];
    const int tid = threadIdx.x, lane = tid & 31, w = tid >> 5;
    int carry = 0;
    for (int base = 0; base < NN; base += 1024) {
        const int i = base + tid;
        const int x = (i < NN) ? g_cnti[i] : 0;
        int v = x;
        #pragma unroll
        for (int off = 1; off < 32; off <<= 1) {
            int t = __shfl_up_sync(0xffffffffu, v, off);
            if (lane >= off) v += t;
        }
        if (lane == 31) wsum[w] = v;
        __syncthreads();
        if (w == 0) {
            int sI = wsum[lane];
            #pragma unroll
            for (int off = 1; off < 32; off <<= 1) {
                int t = __shfl_up_sync(0xffffffffu, sI, off);
                if (lane >= off) sI += t;
            }
            wsum[lane] = sI;
        }
        __syncthreads();
        const int offset = carry + ((w > 0) ? wsum[w - 1] : 0);
        if (i < NN) {
            g_cur[i] = offset + v - x;
            g_icnt[i] = 1.0f / fmaxf((float)x, 1.0f);
        }
        carry += wsum[31];
        __syncthreads();
    }
}

__global__ void k_perm(const int* __restrict__ ei, const float* __restrict__ d,
                       const float* __restrict__ r) {
    int e = blockIdx.x * blockDim.x + threadIdx.x;
    if (e < EE) {
        int dst = ei[e];
        int pos = atomicAdd(&g_cur[dst], 1);
        g_dstS[pos] = dst;
        g_srcS[pos] = ei[EE + e];
        float dd = d[e];
        g_dsrt[pos] = dd;
        float c = (dd < CUTF) ? 0.5f * (cosf(PI_F * dd / CUTF) + 1.0f) : 0.0f;
        g_Cs[pos] = c;
        atomicAdd(&g_cntC[dst], c);
        g_rs[pos * 3 + 0] = r[e * 3 + 0];
        g_rs[pos * 3 + 1] = r[e * 3 + 1];
        g_rs[pos * 3 + 2] = r[e * 3 + 2];
    }
}

// Wc[l] = W3s[l] @ Wn1b[l] ; bc[l] = b3s[l] @ Wn1b[l]
__global__ void k_wc(const float* __restrict__ W3, const float* __restrict__ b3,
                     const float* __restrict__ Wn1) {
    const int l = blockIdx.x;
    const float* w3 = W3 + l * 64 * 134;
    const float* wn1b = Wn1 + l * 256 * 64 + 128 * 64;
    const float* b3l = b3 + l * 134;
    const int tid = threadIdx.x;
    const int o = tid & 63;
    for (int h = tid >> 6; h < 64; h += 4) {
        float acc = 0.0f;
        for (int m = 0; m < 128; m++)
            acc += w3[h * 134 + m] * wn1b[m * 64 + o];
        g_Wc[l * 4096 + h * 64 + o] = acc;
    }
    if (tid < 64) {
        float acc = 0.0f;
        for (int m = 0; m < 128; m++) acc += b3l[m] * wn1b[m * 64 + tid];
        g_bc[l * 64 + tid] = acc;
    }
}

// ---------------- projection (src pointer = s input for layer 0, g_sbuf after) ----------------
#define P_W 0
#define P_X (P_W + 128 * 132)
#define P_TOT (P_X + 64 * 132)

__global__ void __launch_bounds__(256, 2) k_proj(const float* __restrict__ W1,
                                                 const float* __restrict__ sin_) {
    extern __shared__ float sm[];
    float* Ws = sm + P_W;
    float* Xt = sm + P_X;

    const int tid = threadIdx.x;
    for (int i = tid; i < 128 * 128; i += 256) {
        int k = i >> 7, o = i & 127;
        float w = (o < 64) ? W1[k * 64 + o] : W1[(128 + k) * 64 + (o - 64)];
        Ws[o * 132 + k] = w;
    }

    const int wid = tid >> 5, lane = tid & 31;
    const int base = blockIdx.x * TN;
    const int nNd = min(TN, NN - base);

    for (int ii = wid; ii < TN; ii += 8) {
        const int n = base + ii;
        const bool valid = (ii < nNd);
        const float4* sp = (const float4*)&sin_[(valid ? n : 0) * SD];
        float4 x = sp[lane];
        if (!valid) x = make_float4(0.f, 0.f, 0.f, 0.f);
        *(float4*)(Xt + ii * 132 + lane * 4) = x;
    }
    __syncthreads();

    const int oc = tid & 31;
    const int eg = tid >> 5;
    unsigned long long acc[8][4];
    #pragma unroll
    for (int i = 0; i < 8; i++)
        #pragma unroll
        for (int j = 0; j < 4; j++) acc[i][j] = 0ull;

    #pragma unroll 2
    for (int k = 0; k < 128; k += 4) {
        ulonglong2 w[4];
        #pragma unroll
        for (int j = 0; j < 4; j++)
            w[j] = *(const ulonglong2*)(Ws + (oc + 32 * j) * 132 + k);
        #pragma unroll
        for (int i = 0; i < 8; i++) {
            ulonglong2 x = *(const ulonglong2*)(Xt + (eg * 8 + i) * 132 + k);
            #pragma unroll
            for (int j = 0; j < 4; j++) {
                ffma2(acc[i][j], x.x, w[j].x);
                ffma2(acc[i][j], x.y, w[j].y);
            }
        }
    }
    #pragma unroll
    for (int i = 0; i < 8; i++) {
        const int n = base + eg * 8 + i;
        if (eg * 8 + i < nNd) {
            #pragma unroll
            for (int j = 0; j < 4; j++) {
                const int o = oc + 32 * j;
                float val = f2x_sum(acc[i][j]);
                if (o < 64) g_Pa[n * HID + o] = val;
                else        g_Pb[n * HID + (o - 64)] = val;
            }
        }
    }
}

// ---------------- edge kernel (R10 gold config; vsrc pointer added) ----------------
#define E_W2T 0
#define E_W3G (E_W2T + 4352)
#define E_B1  (E_W3G + 416)
#define E_B2  (E_B1 + 64)
#define E_B3G (E_B2 + 64)
#define E_W1D (E_B3G + 16)
#define E_H1  (E_W1D + 64)
#define E_H2  (E_H1 + 4352)
#define E_CS  (E_H2 + 4352)
#define E_DS  (E_CS + 64)
#define E_SS  (E_DS + 64)
#define E_PBN (E_SS + 64)
#define E_TOT (E_PBN + 4096)            // 17968 floats = 71872 B

__device__ __forceinline__ void prefetch_pb(float* PbN, int ntile, int tid) {
    if (ntile < NT_E) {
        const int base2 = ntile * TE;
        const int e = tid >> 2;
        const int epos = min(base2 + e, EE - 1);
        const int se = g_srcS[epos];
        const int f0 = (tid & 3) * 16;
        const float* gp = &g_Pb[se * HID + f0];
        unsigned saddr = (unsigned)__cvta_generic_to_shared(PbN + e * 64 + f0);
        #pragma unroll
        for (int c = 0; c < 4; c++)
            asm volatile("cp.async.cg.shared.global [%0], [%1], 16;"
                         :: "r"(saddr + c * 16), "l"(gp + c * 4) : "memory");
    }
    asm volatile("cp.async.commit_group;" ::: "memory");
}

__global__ void __launch_bounds__(256, 3) k_edge(
    const float* __restrict__ W1, const float* __restrict__ b1,
    const float* __restrict__ W2, const float* __restrict__ b2,
    const float* __restrict__ W3, const float* __restrict__ b3,
    const float* __restrict__ vsrc)
{
    extern __shared__ float sm[];
    float* W2t = sm + E_W2T;
    float* W3g = sm + E_W3G;
    float* b1s = sm + E_B1;
    float* b2s = sm + E_B2;
    float* b3g = sm + E_B3G;
    float* w1d = sm + E_W1D;
    float* H1e = sm + E_H1;
    float* H2e = sm + E_H2;
    float* CS  = sm + E_CS;
    int*   dstSh = (int*)(sm + E_DS);
    int*   srcSh = (int*)(sm + E_SS);
    float* PbN = sm + E_PBN;

    const int tid = threadIdx.x;

    for (int i = tid; i < 64 * 64; i += 256) {
        int k = i >> 6, o = i & 63;
        W2t[o * 68 + k] = W2[k * 64 + o];
    }
    for (int i = tid; i < 6 * 64; i += 256) {
        int o = i % 6, k = i / 6;
        W3g[o * 68 + k] = W3[k * 134 + 128 + o];
    }
    if (tid < 64) {
        b1s[tid] = b1[tid];
        b2s[tid] = b2[tid];
        w1d[tid] = W1[256 * 64 + tid];
    }
    if (tid < 6) b3g[tid] = b3[128 + tid];

    const int wid = tid >> 5, lane = tid & 31;

    prefetch_pb(PbN, blockIdx.x, tid);

    for (int tile = blockIdx.x; tile < NT_E; tile += gridDim.x) {
        const int base = tile * TE;
        const int nE = min(TE, EE - base);

        asm volatile("cp.async.wait_group 0;" ::: "memory");
        __syncthreads();

        // ---- P1: gather + silu -> H1e [e][k] ----
        #pragma unroll 2
        for (int i = 0; i < 8; i++) {
            const int ee = wid * 8 + i;
            const int epos = base + ee;
            const bool valid = (ee < nE);
            int dst = 0, src = 0;
            float dd = 0.0f;
            if (valid) { dst = g_dstS[epos]; src = g_srcS[epos]; dd = g_dsrt[epos]; }
            const float2 a = ((const float2*)&g_Pa[dst * HID])[lane];
            const float2 b = ((const float2*)(PbN + ee * 64))[lane];
            const int k0 = lane * 2;
            float h0 = a.x + b.x + dd * w1d[k0] + b1s[k0];
            float h1 = a.y + b.y + dd * w1d[k0 + 1] + b1s[k0 + 1];
            float2 hv;
            hv.x = valid ? silu_f(h0) : 0.0f;
            hv.y = valid ? silu_f(h1) : 0.0f;
            *(float2*)(H1e + ee * 68 + k0) = hv;
            if (lane == 0) {
                CS[ee] = valid ? g_Cs[epos] : 0.0f;
                dstSh[ee] = dst; srcSh[ee] = src;
            }
        }
        __syncthreads();

        prefetch_pb(PbN, tile + gridDim.x, tid);

        // ---- P2: GEMM2 -> H2e ----
        {
            const int oc = tid & 15;
            const int eg = tid >> 4;
            unsigned long long acc[4][4];
            #pragma unroll
            for (int i = 0; i < 4; i++)
                #pragma unroll
                for (int j = 0; j < 4; j++) acc[i][j] = packlo(b2s[oc + 16 * j]);
            #pragma unroll 4
            for (int k = 0; k < 64; k += 4) {
                ulonglong2 w[4];
                #pragma unroll
                for (int j = 0; j < 4; j++)
                    w[j] = *(const ulonglong2*)(W2t + (oc + 16 * j) * 68 + k);
                #pragma unroll
                for (int i = 0; i < 4; i++) {
                    ulonglong2 x = *(const ulonglong2*)(H1e + (eg * 4 + i) * 68 + k);
                    #pragma unroll
                    for (int j = 0; j < 4; j++) {
                        ffma2(acc[i][j], x.x, w[j].x);
                        ffma2(acc[i][j], x.y, w[j].y);
                    }
                }
            }
            #pragma unroll
            for (int i = 0; i < 4; i++)
                #pragma unroll
                for (int j = 0; j < 4; j++)
                    H2e[(eg * 4 + i) * 68 + oc + 16 * j] = silu_f(f2x_sum(acc[i][j]));
        }
        __syncthreads();

        // ---- P3: scatter C·H2 -> g_hagg (run-reduced) ----
        {
            const int oc2 = (tid & 31) * 2;
            const int eg = tid >> 5;
            int cur = dstSh[eg * 8];
            float s0 = 0.f, s1 = 0.f;
            #pragma unroll
            for (int i = 0; i < 8; i++) {
                const int ee = eg * 8 + i;
                int dd2 = dstSh[ee];
                if (dd2 != cur) {
                    atomicAdd(&g_hagg[cur * HID + oc2], s0);
                    atomicAdd(&g_hagg[cur * HID + oc2 + 1], s1);
                    cur = dd2; s0 = s1 = 0.f;
                }
                float c = CS[ee];
                float2 h2 = *(const float2*)(H2e + ee * 68 + oc2);
                s0 += h2.x * c; s1 += h2.y * c;
            }
            atomicAdd(&g_hagg[cur * HID + oc2], s0);
            atomicAdd(&g_hagg[cur * HID + oc2 + 1], s1);
        }

        // ---- P4: gates + in-warp segmented v-reduce (tid < 64) ----
        if (tid < TE) {
            const int ee = tid;
            const int epos = base + ee;
            unsigned long long g2[6];
            #pragma unroll
            for (int j = 0; j < 6; j++) g2[j] = 0ull;
            #pragma unroll 4
            for (int k = 0; k < 64; k += 4) {
                ulonglong2 x = *(const ulonglong2*)(H2e + ee * 68 + k);
                #pragma unroll
                for (int j = 0; j < 6; j++) {
                    ulonglong2 w = *(const ulonglong2*)(W3g + j * 68 + k);
                    ffma2(g2[j], x.x, w.x);
                    ffma2(g2[j], x.y, w.y);
                }
            }
            float a6[6];
            #pragma unroll
            for (int j = 0; j < 6; j++) a6[j] = b3g[j] + f2x_sum(g2[j]);

            const float c = CS[ee];
            const int src = srcSh[ee];
            const int dst = dstSh[ee];
            float rv[3];
            #pragma unroll
            for (int x = 0; x < 3; x++) rv[x] = (epos < EE) ? g_rs[epos * 3 + x] : 0.0f;
            float m[9];
            #pragma unroll
            for (int vi = 0; vi < 3; vi++) {
                const float gv = a6[vi], gr = a6[3 + vi];
                #pragma unroll
                for (int x = 0; x < 3; x++)
                    m[vi * 3 + x] = (vsrc[src * 9 + vi * 3 + x] * gv + rv[x] * gr) * c;
            }

            const int l16 = lane & 15;
            bool ok[4];
            #pragma unroll
            for (int s9 = 0; s9 < 4; s9++) {
                int off = 1 << s9;
                int ud = __shfl_up_sync(0xffffffffu, dst, off);
                ok[s9] = (l16 >= off) && (ud == dst);
            }
            int nd = __shfl_down_sync(0xffffffffu, dst, 1);
            const bool tail = (l16 == 15) || (nd != dst);
            #pragma unroll
            for (int col = 0; col < 9; col++) {
                float vv = m[col];
                #pragma unroll
                for (int s9 = 0; s9 < 4; s9++) {
                    float uv = __shfl_up_sync(0xffffffffu, vv, 1 << s9);
                    if (ok[s9]) vv += uv;
                }
                if (tail) atomicAdd(&g_vagg[dst * 9 + col], vv);
            }
        }
    }
}

// ---------------- node kernel (R10 gold + input pointers + fused output) ----------------
#define N_W1T 0
#define N_W2T (N_W1T + 12800)
#define N_B2  (N_W2T + 8704)
#define N_BN1 (N_B2 + 128)
#define N_BC  (N_BN1 + 64)
#define N_CT  (N_BC + 64)
#define N_XT  (N_CT + 64)
#define N_UT  (N_XT + 12800)
#define N_TOT (N_UT + 4352)              // 38976 floats = 155904 B

__global__ void __launch_bounds__(256, 1) k_node(
    const float* __restrict__ Wn1, const float* __restrict__ bn1,
    const float* __restrict__ Wn2, const float* __restrict__ bn2,
    const float* __restrict__ Wc, const float* __restrict__ bc,
    const float* __restrict__ sin_, const float* __restrict__ vin_,
    float* __restrict__ out, int last)
{
    extern __shared__ float sm[];
    float* W1t = sm + N_W1T;
    float* W2t = sm + N_W2T;
    float* b2s = sm + N_B2;
    float* bn1s = sm + N_BN1;
    float* bcs = sm + N_BC;
    float* CT  = sm + N_CT;
    float* Xt  = sm + N_XT;
    float* Ut  = sm + N_UT;

    const int tid = threadIdx.x;
    for (int i = tid; i < 64 * 128; i += 256) {
        int k = i >> 6, o = i & 63;
        W1t[o * 200 + k] = Wn1[k * 64 + o];
    }
    for (int i = tid; i < 64 * 64; i += 256) {
        int k = i >> 6, o = i & 63;
        W1t[o * 200 + 128 + k] = Wc[k * 64 + o];
    }
    for (int i = tid; i < 128 * 64; i += 256) {
        int k = i >> 7, o = i & 127;
        W2t[o * 68 + k] = Wn2[k * 128 + o];
    }
    if (tid < 64) { bn1s[tid] = bn1[tid]; bcs[tid] = bc[tid]; }
    if (tid < 128) b2s[tid] = bn2[tid];
    __syncthreads();

    const int wid = tid >> 5, lane = tid & 31;

    for (int tile = blockIdx.x; tile < NT_N; tile += gridDim.x) {
        const int base = tile * TN;
        const int nNd = min(TN, NN - base);

        for (int ii = wid; ii < TN; ii += 8) {
            const int n = base + ii;
            const bool valid = (ii < nNd);
            const float4* sp = (const float4*)&sin_[(valid ? n : 0) * SD];
            float4 xs = sp[lane];
            if (!valid) xs = make_float4(0, 0, 0, 0);
            *(float4*)(Xt + ii * 200 + lane * 4) = xs;
            if (lane < 16) {
                float4* hp = (float4*)&g_hagg[(valid ? n : 0) * HID];
                float4 xh = hp[lane];
                if (!valid) xh = make_float4(0, 0, 0, 0);
                *(float4*)(Xt + ii * 200 + 128 + lane * 4) = xh;
                if (valid) hp[lane] = make_float4(0, 0, 0, 0);
            }
        }
        if (tid < 64) CT[tid] = (tid < nNd) ? g_cntC[base + tid] : 0.0f;

        // fused v update (reads vin_, writes g_vbuf [+ out on last layer])
        for (int idx = tid; idx < TN * 9; idx += 256) {
            const int nn = base + idx / 9;
            if (idx / 9 < nNd) {
                const int col = idx % 9;
                float va = g_vagg[nn * 9 + col];
                float nv = vin_[nn * 9 + col] + va * g_icnt[nn];
                g_vbuf[nn * 9 + col] = nv;
                g_vagg[nn * 9 + col] = 0.0f;
                if (last) out[NN * SD + nn * 9 + col] = nv;
            }
        }
        __syncthreads();

        // GEMM1: Ut = silu(s@Wn1a + hagg@Wc + cntC*bc + bn1)   (k = 192)
        {
            const int oc = tid & 15;
            const int eg = tid >> 4;
            unsigned long long acc[4][4];
            #pragma unroll
            for (int i = 0; i < 4; i++) {
                float ci = CT[eg * 4 + i];
                #pragma unroll
                for (int j = 0; j < 4; j++)
                    acc[i][j] = packlo(bn1s[oc + 16 * j] + ci * bcs[oc + 16 * j]);
            }
            #pragma unroll 2
            for (int k = 0; k < 192; k += 4) {
                ulonglong2 w[4];
                #pragma unroll
                for (int j = 0; j < 4; j++)
                    w[j] = *(const ulonglong2*)(W1t + (oc + 16 * j) * 200 + k);
                #pragma unroll
                for (int i = 0; i < 4; i++) {
                    ulonglong2 x = *(const ulonglong2*)(Xt + (eg * 4 + i) * 200 + k);
                    #pragma unroll
                    for (int j = 0; j < 4; j++) {
                        ffma2(acc[i][j], x.x, w[j].x);
                        ffma2(acc[i][j], x.y, w[j].y);
                    }
                }
            }
            #pragma unroll
            for (int i = 0; i < 4; i++)
                #pragma unroll
                for (int j = 0; j < 4; j++)
                    Ut[(eg * 4 + i) * 68 + oc + 16 * j] = silu_f(f2x_sum(acc[i][j]));
        }
        __syncthreads();

        // GEMM2: sbuf = sin + Ut @ Wn2 + bn2  [+ out on last layer]
        {
            const int oc = tid & 31;
            const int eg = tid >> 5;
            unsigned long long acc[8][4];
            #pragma unroll
            for (int i = 0; i < 8; i++)
                #pragma unroll
                for (int j = 0; j < 4; j++) acc[i][j] = packlo(b2s[oc + 32 * j]);
            #pragma unroll 4
            for (int k = 0; k < 64; k += 4) {
                ulonglong2 w[4];
                #pragma unroll
                for (int j = 0; j < 4; j++)
                    w[j] = *(const ulonglong2*)(W2t + (oc + 32 * j) * 68 + k);
                #pragma unroll
                for (int i = 0; i < 8; i++) {
                    ulonglong2 x = *(const ulonglong2*)(Ut + (eg * 8 + i) * 68 + k);
                    #pragma unroll
                    for (int j = 0; j < 4; j++) {
                        ffma2(acc[i][j], x.x, w[j].x);
                        ffma2(acc[i][j], x.y, w[j].y);
                    }
                }
            }
            #pragma unroll
            for (int i = 0; i < 8; i++) {
                const int n = base + eg * 8 + i;
                if (eg * 8 + i < nNd) {
                    #pragma unroll
                    for (int j = 0; j < 4; j++) {
                        const int idx = n * SD + oc + 32 * j;
                        float nv = sin_[idx] + f2x_sum(acc[i][j]);
                        g_sbuf[idx] = nv;
                        if (last) out[idx] = nv;
                    }
                }
            }
        }
        __syncthreads();
    }
}

// ---------------- host launch ----------------
extern "C" void kernel_launch(void* const* d_in, const int* in_sizes, int n_in,
                              void* d_out, int out_size) {
    const float* s   = (const float*)d_in[0];
    const float* v   = (const float*)d_in[1];
    const int*   ei  = (const int*)d_in[2];
    const float* d   = (const float*)d_in[3];
    const float* r   = (const float*)d_in[4];
    const float* W1  = (const float*)d_in[5];
    const float* b1  = (const float*)d_in[6];
    const float* W2  = (const float*)d_in[7];
    const float* b2  = (const float*)d_in[8];
    const float* W3  = (const float*)d_in[9];
    const float* b3  = (const float*)d_in[10];
    const float* Wn1 = (const float*)d_in[11];
    const float* bn1 = (const float*)d_in[12];
    const float* Wn2 = (const float*)d_in[13];
    const float* bn2 = (const float*)d_in[14];
    float* out = (float*)d_out;

    const int psm = P_TOT * 4;
    const int esm = E_TOT * 4;
    const int nsm = N_TOT * 4;
    cudaFuncSetAttribute(k_proj, cudaFuncAttributeMaxDynamicSharedMemorySize, psm);
    cudaFuncSetAttribute(k_edge, cudaFuncAttributeMaxDynamicSharedMemorySize, esm);
    cudaFuncSetAttribute(k_node, cudaFuncAttributeMaxDynamicSharedMemorySize, nsm);

    float* d_sbuf; cudaGetSymbolAddress((void**)&d_sbuf, g_sbuf);
    float* d_vbuf; cudaGetSymbolAddress((void**)&d_vbuf, g_vbuf);
    float* d_Wc;   cudaGetSymbolAddress((void**)&d_Wc, g_Wc);
    float* d_bc;   cudaGetSymbolAddress((void**)&d_bc, g_bc);

    k_init<<<1024, 256>>>();
    k_cnt<<<(EE + 255) / 256, 256>>>(ei);
    k_scan<<<1, 1024>>>();
    k_perm<<<(EE + 255) / 256, 256>>>(ei, d, r);
    k_wc<<<DEPTH, 256>>>(W3, b3, Wn1);

    for (int l = 0; l < DEPTH; l++) {
        const float* sin_ = (l == 0) ? s : d_sbuf;
        const float* vin_ = (l == 0) ? v : d_vbuf;
        k_proj<<<NT_N, 256, psm>>>(W1 + l * 257 * 64, sin_);
        k_edge<<<456, 256, esm>>>(W1 + l * 257 * 64, b1 + l * 64,
                                  W2 + l * 64 * 64, b2 + l * 64,
                                  W3 + l * 64 * 134, b3 + l * 134, vin_);
        k_node<<<152, 256, nsm>>>(Wn1 + l * 256 * 64, bn1 + l * 64,
                                  Wn2 + l * 64 * 128, bn2 + l * 128,
                                  d_Wc + l * 4096, d_bc + l * 64,
                                  sin_, vin_, out, (l == DEPTH - 1) ? 1 : 0);
    }
}